// round 7
// baseline (speedup 1.0000x reference)
#include <cuda_runtime.h>

#define BATCH   256
#define INDIM   159
#define MDIM    93
#define MATEL   2976
#define LINDIM  (MDIM + MATEL)   /* 3069 */
#define KPATH   64
#define SIGDIM  340

typedef unsigned long long u64;

__device__ float g_lin[BATCH * LINDIM];
__device__ float g_lgt[2 * BATCH * 10];
__device__ int   g_cnt[BATCH];          // zero-init (.bss); restored to 0 each run

// ---------------- packed f32x2 helpers (sm_100+ PTX) -----------------------
__device__ __forceinline__ u64 pk2(float lo, float hi) {
    u64 r; asm("mov.b64 %0, {%1, %2};" : "=l"(r) : "f"(lo), "f"(hi)); return r;
}
__device__ __forceinline__ u64 bc2(float x) {
    u64 r; asm("mov.b64 %0, {%1, %1};" : "=l"(r) : "f"(x)); return r;
}
__device__ __forceinline__ void unpk2(u64 p, float& lo, float& hi) {
    asm("mov.b64 {%0, %1}, %2;" : "=f"(lo), "=f"(hi) : "l"(p));
}
__device__ __forceinline__ u64 fma2(u64 a, u64 b, u64 c) {
    u64 d; asm("fma.rn.f32x2 %0, %1, %2, %3;" : "=l"(d) : "l"(a), "l"(b), "l"(c)); return d;
}
__device__ __forceinline__ u64 mul2(u64 a, u64 b) {
    u64 d; asm("mul.rn.f32x2 %0, %1, %2;" : "=l"(d) : "l"(a), "l"(b)); return d;
}
__device__ __forceinline__ u64 add2(u64 a, u64 b) {
    u64 d; asm("add.rn.f32x2 %0, %1, %2;" : "=l"(d) : "l"(a), "l"(b)); return d;
}

// ---------------------------------------------------------------------------
// Kernel 1: lin = x @ [W_mean; W_cov]^T + bias.  32-batch tiles, transposed x
// staging, f32x2 inner loop (16 batch-pairs per thread-row).
// ---------------------------------------------------------------------------
__global__ void __launch_bounds__(128) k_linear(
    const float* __restrict__ x,
    const float* __restrict__ Wm, const float* __restrict__ bm,
    const float* __restrict__ Wc, const float* __restrict__ bc)
{
    __shared__ float xt[INDIM][32];     // transposed; broadcast reads -> no conflicts
    __shared__ float Ws[128][33];
    const int tid = threadIdx.x;
    const int b0  = blockIdx.y * 32;
    const int r0  = blockIdx.x * 128;

    for (int e = tid; e < 32 * INDIM; e += 128) {
        int bb = e / INDIM, c = e % INDIM;
        xt[c][bb] = x[(b0 + bb) * INDIM + c];
    }

    const int r = r0 + tid;
    float bias = 0.f;
    if (r < LINDIM) bias = (r < MDIM) ? bm[r] : bc[r - MDIM];
    const u64 biasb = bc2(bias);
    u64 acc2[16];
#pragma unroll
    for (int p = 0; p < 16; p++) acc2[p] = biasb;   // bias on EVERY batch pair

    for (int ct = 0; ct < INDIM; ct += 32) {
        const int cn = min(32, INDIM - ct);
        __syncthreads();
        for (int e = tid; e < 128 * 32; e += 128) {
            int rr = e >> 5, cc = e & 31;
            int rg = r0 + rr;
            float w = 0.f;
            if (rg < LINDIM && cc < cn)
                w = (rg < MDIM) ? Wm[rg * INDIM + ct + cc]
                                : Wc[(rg - MDIM) * INDIM + ct + cc];
            Ws[rr][cc] = w;
        }
        __syncthreads();
        for (int cc = 0; cc < cn; cc++) {
            const u64 w2 = bc2(Ws[tid][cc]);
            const u64* xp = (const u64*)&xt[ct + cc][0];
#pragma unroll
            for (int p = 0; p < 16; p++) acc2[p] = fma2(w2, xp[p], acc2[p]);
        }
    }
    if (r < LINDIM) {
#pragma unroll
        for (int p = 0; p < 16; p++) {
            float lo, hi; unpk2(acc2[p], lo, hi);
            g_lin[(b0 + 2 * p) * LINDIM + r]     = lo;
            g_lin[(b0 + 2 * p + 1) * LINDIM + r] = hi;
        }
    }
}

// ---------------------------------------------------------------------------
// Kernel 2 (fused): newV + signatures + normalization + partial logits +
// inline softmax via arrival counter.  256 threads, grid 2*BATCH.
// 8 lanes per path: lane owns (a = leading index, g = bq-half); f32x2 packs
// the two adjacent bq values.  State/lane: S4 16 u64, S3 4 u64, S2 1 u64, S1.
// ---------------------------------------------------------------------------
__device__ __forceinline__ void chen8(
    float& S1a, u64& S2p, u64* S3p, u64* S4p,
    float d0, float d1, float d2, float d3,
    float da, float dg0, float dg1, u64 halfb)
{
    u64 db[4];
    db[0] = bc2(d0); db[1] = bc2(d1); db[2] = bc2(d2); db[3] = bc2(d3);
    const u64 dpg = pk2(dg0, dg1);

    // level 4: S4[c][e] += (S3[c] + (0.5*(S2+g4*d_bq))*d[c]) * d[e]
    const float g4 = fmaf(0.25f, da, S1a) * (1.f / 3.f);
    const u64 rph = mul2(halfb, fma2(bc2(g4), dpg, S2p));
#pragma unroll
    for (int c = 0; c < 4; c++) {
        const u64 t = fma2(rph, db[c], S3p[c]);
#pragma unroll
        for (int e = 0; e < 4; e++)
            S4p[c * 4 + e] = fma2(t, db[e], S4p[c * 4 + e]);
    }
    // level 3: S3[c] += (S2 + (0.5*g3)*d_bq) * d[c]
    const float g3h = 0.5f * fmaf(1.f / 3.f, da, S1a);
    const u64 wp = fma2(bc2(g3h), dpg, S2p);
#pragma unroll
    for (int c = 0; c < 4; c++)
        S3p[c] = fma2(wp, db[c], S3p[c]);
    // level 2
    S2p = fma2(bc2(fmaf(0.5f, da, S1a)), dpg, S2p);
    S1a += da;
}

__device__ __forceinline__ u64 psum4(u64 v)   // sum the 4 paths of a warp
{
    v = add2(v, __shfl_down_sync(0xffffffffu, v, 16));
    v = add2(v, __shfl_down_sync(0xffffffffu, v, 8));
    return v;
}

__global__ void __launch_bounds__(256, 2) k_sigf(
    const float* __restrict__ x, const float* __restrict__ eps,
    const float* __restrict__ Wf, const float* __restrict__ bf,
    float* __restrict__ out)
{
    __shared__ float xs[INDIM];
    __shared__ float covm[LINDIM];          // mean [0:93), cov [93:3069)
    __shared__ float nvs[MDIM * 32];
    __shared__ float eps_red[MDIM * 32];    // eps slice; re-used as red[8*SIGDIM]
    __shared__ int   arrive_s;

    const int blk = blockIdx.x;
    const int b = blk >> 1, h = blk & 1;
    const int tid = threadIdx.x;

    for (int e = tid; e < INDIM; e += 256) xs[e] = x[b * INDIM + e];
    for (int e = tid; e < LINDIM; e += 256) covm[e] = g_lin[b * LINDIM + e];
    for (int e = tid; e < MDIM * 32; e += 256) {
        int j = e >> 5, kk = e & 31;
        eps_red[e] = eps[(b * MDIM + j) * KPATH + h * 32 + kk];
    }
    __syncthreads();

    // ---- newV for this block's 32 k's (f32x2 over k-pairs) ----
    {
        const int kp = tid & 15;        // k-pair 0..15
        const int ig = tid >> 4;        // 0..15
        for (int i = ig; i < MDIM; i += 16) {
            const int X = i / 3, tr = i % 3;
            const int tbase = 93 + tr * (tr + 1) / 2;
            u64 acc = bc2(covm[i]);
            for (int y = 0; y <= X; y++) {
                const int d = X - y;
                const int blk6 = (31 * d - (d * (d - 1)) / 2 + y) * 6 + tbase;
#pragma unroll
                for (int tc = 0; tc < 3; tc++) {
                    if (tc <= tr) {
                        const u64 ep = *(const u64*)&eps_red[(y * 3 + tc) * 32 + 2 * kp];
                        acc = fma2(bc2(covm[blk6 + tc]), ep, acc);
                    }
                }
            }
            *(u64*)&nvs[i * 32 + 2 * kp] = acc;
        }
    }
    __syncthreads();

    // ---- signature recursion (8 lanes per path) ----
    const int pk = tid >> 3;        // path 0..31
    const int l8 = tid & 7;
    const int a  = l8 >> 1;         // leading tensor index
    const int g  = l8 & 1;          // bq-half: owns bq = 2g, 2g+1
    const u64 halfb = bc2(0.5f);

    float S1a = 0.f;
    u64 S2p = 0ull;
    u64 S3p[4], S4p[16];
#pragma unroll
    for (int i = 0; i < 4; i++)  S3p[i] = 0ull;
#pragma unroll
    for (int i = 0; i < 16; i++) S4p[i] = 0ull;

    float p0 = xs[0], p1 = xs[1], p2 = xs[2], p3 = xs[96];
    for (int m = 0; m < 31; m++) {
        float q0 = nvs[(3 * m + 0) * 32 + pk];
        float q1 = nvs[(3 * m + 1) * 32 + pk];
        float q2 = nvs[(3 * m + 2) * 32 + pk];
        float qt = xs[128 + m];
        {
            float d0 = q0 - p0, d1 = q1 - p1, d2 = q2 - p2, d3 = qt - p3;
            float da  = (a & 2) ? ((a & 1) ? d3 : d2) : ((a & 1) ? d1 : d0);
            float dg0 = g ? d2 : d0, dg1 = g ? d3 : d1;
            chen8(S1a, S2p, S3p, S4p, d0, d1, d2, d3, da, dg0, dg1, halfb);
        }
        p0 = q0; p1 = q1; p2 = q2; p3 = qt;
        q0 = xs[3 * (m + 1) + 0];
        q1 = xs[3 * (m + 1) + 1];
        q2 = xs[3 * (m + 1) + 2];
        qt = xs[96 + m + 1];
        {
            float d0 = q0 - p0, d1 = q1 - p1, d2 = q2 - p2, d3 = qt - p3;
            float da  = (a & 2) ? ((a & 1) ? d3 : d2) : ((a & 1) ? d1 : d0);
            float dg0 = g ? d2 : d0, dg1 = g ? d3 : d1;
            chen8(S1a, S2p, S3p, S4p, d0, d1, d2, d3, da, dg0, dg1, halfb);
        }
        p0 = q0; p1 = q1; p2 = q2; p3 = qt;
    }

    // ---- per-path norms (S1 replicated in both g-lanes: count once) ----
    float n1 = (g == 0) ? S1a * S1a : 0.f;
    float n2 = 0.f, n3 = 0.f, n4 = 0.f;
    { float lo, hi; unpk2(S2p, lo, hi); n2 = fmaf(lo, lo, n2); n2 = fmaf(hi, hi, n2); }
#pragma unroll
    for (int i = 0; i < 4; i++)  { float lo, hi; unpk2(S3p[i], lo, hi); n3 = fmaf(lo, lo, n3); n3 = fmaf(hi, hi, n3); }
#pragma unroll
    for (int i = 0; i < 16; i++) { float lo, hi; unpk2(S4p[i], lo, hi); n4 = fmaf(lo, lo, n4); n4 = fmaf(hi, hi, n4); }
#pragma unroll
    for (int msk = 1; msk <= 4; msk <<= 1) {
        n1 += __shfl_xor_sync(0xffffffffu, n1, msk);
        n2 += __shfl_xor_sync(0xffffffffu, n2, msk);
        n3 += __shfl_xor_sync(0xffffffffu, n3, msk);
        n4 += __shfl_xor_sync(0xffffffffu, n4, msk);
    }
    const float norm2 = 1.f + n1 + n2 + n3 + n4;
    const float psi = (norm2 <= 4.f) ? norm2 : (8.f - 16.f / norm2);
    float lo_ = 0.f, hi_ = 1.f;
    for (int it = 0; it < 40; it++) {
        float mid = 0.5f * (lo_ + hi_);
        float m2 = mid * mid, m4 = m2 * m2;
        float val = 1.f + m2 * n1 + m4 * n2 + (m4 * m2) * n3 + (m4 * m4) * n4;
        bool pos = val > psi;
        hi_ = pos ? mid : hi_;
        lo_ = pos ? lo_ : mid;
    }
    const float lam = 0.5f * (lo_ + hi_);
    const float l2 = lam * lam, l3 = l2 * lam, l4 = l2 * l2;
    S1a *= lam;
    const u64 l2b = bc2(l2), l3b = bc2(l3), l4b = bc2(l4);
    S2p = mul2(l2b, S2p);
#pragma unroll
    for (int i = 0; i < 4; i++)  S3p[i] = mul2(l3b, S3p[i]);
#pragma unroll
    for (int i = 0; i < 16; i++) S4p[i] = mul2(l4b, S4p[i]);

    // ---- reduce 4 paths of each warp; lanes 0..7 hold slice sums ----
    __syncthreads();                 // eps no longer needed
    float* red = eps_red;            // 8 warps x SIGDIM = 2720 <= 2976
    const int w = tid >> 5;
    const int lane = tid & 31;
    {
        float v = S1a;
        v += __shfl_down_sync(0xffffffffu, v, 16);
        v += __shfl_down_sync(0xffffffffu, v, 8);
        if (lane < 8 && (lane & 1) == 0) red[w * SIGDIM + (lane >> 1)] = v;
    }
    {
        u64 v = psum4(S2p);
        if (lane < 8) {
            float lo, hi; unpk2(v, lo, hi);
            const int aa = lane >> 1, gg = lane & 1;
            red[w * SIGDIM + 4 + aa * 4 + 2 * gg]     = lo;
            red[w * SIGDIM + 4 + aa * 4 + 2 * gg + 1] = hi;
        }
    }
#pragma unroll
    for (int c = 0; c < 4; c++) {
        u64 v = psum4(S3p[c]);
        if (lane < 8) {
            float lo, hi; unpk2(v, lo, hi);
            const int aa = lane >> 1, gg = lane & 1;
            red[w * SIGDIM + 20 + aa * 16 + (2 * gg) * 4 + c]     = lo;
            red[w * SIGDIM + 20 + aa * 16 + (2 * gg + 1) * 4 + c] = hi;
        }
    }
#pragma unroll
    for (int i = 0; i < 16; i++) {
        const int c = i >> 2, e = i & 3;
        u64 v = psum4(S4p[i]);
        if (lane < 8) {
            float lo, hi; unpk2(v, lo, hi);
            const int aa = lane >> 1, gg = lane & 1;
            red[w * SIGDIM + 84 + aa * 64 + (2 * gg) * 16 + c * 4 + e]     = lo;
            red[w * SIGDIM + 84 + aa * 64 + (2 * gg + 1) * 16 + c * 4 + e] = hi;
        }
    }
    __syncthreads();
    for (int e = tid; e < SIGDIM; e += 256) {
        float sum = 0.f;
#pragma unroll
        for (int ww = 0; ww < 8; ww++) sum += red[ww * SIGDIM + e];
        red[e] = sum;
    }
    __syncthreads();

    // ---- partial logits for this half-batch ----
    for (int c = w; c < 10; c += 8) {
        float acc = 0.f;
        for (int sidx = lane; sidx < SIGDIM; sidx += 32)
            acc = fmaf(red[sidx], Wf[c * SIGDIM + sidx], acc);
#pragma unroll
        for (int off = 16; off >= 1; off >>= 1)
            acc += __shfl_xor_sync(0xffffffffu, acc, off);
        if (lane == 0) g_lgt[blk * 10 + c] = acc;
    }
    __syncthreads();

    // ---- arrival counter: second block for this b does the softmax ----
    if (tid == 0) {
        __threadfence();
        arrive_s = atomicAdd(&g_cnt[b], 1);
    }
    __syncthreads();
    if (arrive_s == 1 && w == 0) {
        __threadfence();
        float v = -3.0e38f;
        if (lane < 10)
            v = (g_lgt[(2 * b) * 10 + lane] + g_lgt[(2 * b + 1) * 10 + lane])
                * (1.f / 64.f) + bf[lane];
        float mx = v;
#pragma unroll
        for (int off = 16; off >= 1; off >>= 1)
            mx = fmaxf(mx, __shfl_xor_sync(0xffffffffu, mx, off));
        float ex = (lane < 10) ? expf(v - mx) : 0.f;
        float se = ex;
#pragma unroll
        for (int off = 16; off >= 1; off >>= 1)
            se += __shfl_xor_sync(0xffffffffu, se, off);
        const float lse = mx + logf(se);
        if (lane < 10) out[b * 10 + lane] = v - lse;
        if (lane == 0) g_cnt[b] = 0;   // restore for next graph replay
    }
}

// ---------------------------------------------------------------------------
extern "C" void kernel_launch(void* const* d_in, const int* in_sizes, int n_in,
                              void* d_out, int out_size)
{
    const float* x   = (const float*)d_in[0];
    const float* Wm  = (const float*)d_in[1];
    const float* bm  = (const float*)d_in[2];
    const float* Wc  = (const float*)d_in[3];
    const float* bc  = (const float*)d_in[4];
    const float* Wf  = (const float*)d_in[5];
    const float* bf  = (const float*)d_in[6];
    const float* eps = (const float*)d_in[7];
    float* out = (float*)d_out;

    k_linear<<<dim3(24, 8), 128>>>(x, Wm, bm, Wc, bc);
    k_sigf<<<2 * BATCH, 256>>>(x, eps, Wf, bf, out);
}

// round 8
// speedup vs baseline: 1.1465x; 1.1465x over previous
#include <cuda_runtime.h>

#define BATCH   256
#define INDIM   159
#define MDIM    93
#define MATEL   2976
#define LINDIM  (MDIM + MATEL)   /* 3069 */
#define KPATH   64
#define SIGDIM  340

typedef unsigned long long u64;

__device__ float g_lin[BATCH * LINDIM];
__device__ float g_lgt[4 * BATCH * 10];
__device__ int   g_cnt[BATCH];          // zero-init (.bss); restored to 0 each run

// ---------------- packed f32x2 helpers (sm_100+ PTX) -----------------------
__device__ __forceinline__ u64 pk2(float lo, float hi) {
    u64 r; asm("mov.b64 %0, {%1, %2};" : "=l"(r) : "f"(lo), "f"(hi)); return r;
}
__device__ __forceinline__ u64 bc2(float x) {
    u64 r; asm("mov.b64 %0, {%1, %1};" : "=l"(r) : "f"(x)); return r;
}
__device__ __forceinline__ void unpk2(u64 p, float& lo, float& hi) {
    asm("mov.b64 {%0, %1}, %2;" : "=f"(lo), "=f"(hi) : "l"(p));
}
__device__ __forceinline__ u64 fma2(u64 a, u64 b, u64 c) {
    u64 d; asm("fma.rn.f32x2 %0, %1, %2, %3;" : "=l"(d) : "l"(a), "l"(b), "l"(c)); return d;
}
__device__ __forceinline__ u64 mul2(u64 a, u64 b) {
    u64 d; asm("mul.rn.f32x2 %0, %1, %2;" : "=l"(d) : "l"(a), "l"(b)); return d;
}
__device__ __forceinline__ u64 add2(u64 a, u64 b) {
    u64 d; asm("add.rn.f32x2 %0, %1, %2;" : "=l"(d) : "l"(a), "l"(b)); return d;
}

// ---------------------------------------------------------------------------
// Kernel 1: lin = x @ [W_mean; W_cov]^T + bias.
// Block: 128 rows x 32 batches.  Thread (rowt = tid&31, bpt = tid>>5) owns
// 4 rows (rowt+32j) x 4 batch-pairs (4*bpt+i): 8 LDS per 16 fma2.
// ---------------------------------------------------------------------------
__global__ void __launch_bounds__(128) k_linear(
    const float* __restrict__ x,
    const float* __restrict__ Wm, const float* __restrict__ bm,
    const float* __restrict__ Wc, const float* __restrict__ bc)
{
    __shared__ float xt[INDIM][32];     // transposed x tile
    __shared__ float Ws[128][33];
    const int tid = threadIdx.x;
    const int b0  = blockIdx.y * 32;
    const int r0  = blockIdx.x * 128;
    const int rowt = tid & 31;
    const int bpt  = tid >> 5;          // warp id = batch-pair group

    for (int e = tid; e < 32 * INDIM; e += 128) {
        int bb = e / INDIM, c = e % INDIM;
        xt[c][bb] = x[(b0 + bb) * INDIM + c];
    }

    u64 acc2[4][4];
    float bias_j[4];
#pragma unroll
    for (int j = 0; j < 4; j++) {
        const int rg = r0 + rowt + 32 * j;
        float bias = 0.f;
        if (rg < LINDIM) bias = (rg < MDIM) ? bm[rg] : bc[rg - MDIM];
        bias_j[j] = bias;
        const u64 bb2 = bc2(bias);
#pragma unroll
        for (int i = 0; i < 4; i++) acc2[j][i] = bb2;
    }
    (void)bias_j;

    for (int ct = 0; ct < INDIM; ct += 32) {
        const int cn = min(32, INDIM - ct);
        __syncthreads();
        for (int e = tid; e < 128 * 32; e += 128) {
            int rr = e >> 5, cc = e & 31;
            int rg = r0 + rr;
            float w = 0.f;
            if (rg < LINDIM && cc < cn)
                w = (rg < MDIM) ? Wm[rg * INDIM + ct + cc]
                                : Wc[(rg - MDIM) * INDIM + ct + cc];
            Ws[rr][cc] = w;
        }
        __syncthreads();
        for (int cc = 0; cc < cn; cc++) {
            u64 w2[4], xp[4];
#pragma unroll
            for (int j = 0; j < 4; j++) w2[j] = bc2(Ws[rowt + 32 * j][cc]);
#pragma unroll
            for (int i = 0; i < 4; i++)
                xp[i] = *(const u64*)&xt[ct + cc][2 * (4 * bpt + i)];
#pragma unroll
            for (int j = 0; j < 4; j++)
#pragma unroll
                for (int i = 0; i < 4; i++)
                    acc2[j][i] = fma2(w2[j], xp[i], acc2[j][i]);
        }
    }
#pragma unroll
    for (int j = 0; j < 4; j++) {
        const int rg = r0 + rowt + 32 * j;
        if (rg < LINDIM) {
#pragma unroll
            for (int i = 0; i < 4; i++) {
                float lo, hi; unpk2(acc2[j][i], lo, hi);
                const int p = 4 * bpt + i;
                g_lin[(b0 + 2 * p) * LINDIM + rg]     = lo;
                g_lin[(b0 + 2 * p + 1) * LINDIM + rg] = hi;
            }
        }
    }
}

// ---------------------------------------------------------------------------
// Kernel 2 (fused): newV + signatures + normalization + partial logits +
// inline softmax via arrival counter.
// 64 threads/block, grid 4*BATCH (quarter of K per block -> ~1 perfect wave
// at 7 blocks/SM).  4 lanes per path, state packed over bq pairs (f32x2).
// ---------------------------------------------------------------------------
struct SigP {
    float S1;
    u64 S2p[2];
    u64 S3p[8];    // [j*4 + c]
    u64 S4p[32];   // [(j*4 + c)*4 + e]
};

__device__ __forceinline__ void chen_step_p(
    SigP& s, float d0, float d1, float d2, float d3, float da, u64 halfb)
{
    u64 db[4], dp[2];
    db[0] = bc2(d0); db[1] = bc2(d1); db[2] = bc2(d2); db[3] = bc2(d3);
    dp[0] = pk2(d0, d1); dp[1] = pk2(d2, d3);

    // level 4: S4[bq][c][e] += (S3[bq][c] + (0.5*(S2[bq]+g4*d[bq]))*d[c]) * d[e]
    const float g4 = fmaf(0.25f, da, s.S1) * (1.f / 3.f);
    const u64 g4b = bc2(g4);
    u64 rph[2];
    rph[0] = mul2(halfb, fma2(g4b, dp[0], s.S2p[0]));
    rph[1] = mul2(halfb, fma2(g4b, dp[1], s.S2p[1]));
#pragma unroll
    for (int j = 0; j < 2; j++) {
#pragma unroll
        for (int c = 0; c < 4; c++) {
            const u64 t = fma2(rph[j], db[c], s.S3p[j * 4 + c]);
#pragma unroll
            for (int e = 0; e < 4; e++)
                s.S4p[(j * 4 + c) * 4 + e] = fma2(t, db[e], s.S4p[(j * 4 + c) * 4 + e]);
        }
    }
    // level 3: S3[bq][c] += (S2[bq] + (0.5*g3)*d[bq]) * d[c]
    const float g3h = 0.5f * fmaf(1.f / 3.f, da, s.S1);
    const u64 g3hb = bc2(g3h);
    u64 wp[2];
    wp[0] = fma2(g3hb, dp[0], s.S2p[0]);
    wp[1] = fma2(g3hb, dp[1], s.S2p[1]);
#pragma unroll
    for (int j = 0; j < 2; j++)
#pragma unroll
        for (int c = 0; c < 4; c++)
            s.S3p[j * 4 + c] = fma2(wp[j], db[c], s.S3p[j * 4 + c]);
    // level 2
    const u64 g2b = bc2(fmaf(0.5f, da, s.S1));
    s.S2p[0] = fma2(g2b, dp[0], s.S2p[0]);
    s.S2p[1] = fma2(g2b, dp[1], s.S2p[1]);
    s.S1 += da;
}

__device__ __forceinline__ u64 wredp(u64 v)   // sum the 8 paths of a warp
{
    v = add2(v, __shfl_down_sync(0xffffffffu, v, 16));
    v = add2(v, __shfl_down_sync(0xffffffffu, v, 8));
    v = add2(v, __shfl_down_sync(0xffffffffu, v, 4));
    return v;
}

__global__ void __launch_bounds__(64, 7) k_sigf(
    const float* __restrict__ x, const float* __restrict__ eps,
    const float* __restrict__ Wf, const float* __restrict__ bf,
    float* __restrict__ out)
{
    __shared__ float xs[INDIM];
    __shared__ float covm[LINDIM];          // mean [0:93), cov [93:3069)
    __shared__ float nvs[MDIM * 16];
    __shared__ float eps_red[MDIM * 16];    // eps slice; re-used as red[2*SIGDIM]
    __shared__ int   arrive_s;

    const int blk = blockIdx.x;
    const int b = blk >> 2, q = blk & 3;    // quarter of K
    const int tid = threadIdx.x;

    for (int e = tid; e < INDIM; e += 64) xs[e] = x[b * INDIM + e];
    for (int e = tid; e < LINDIM; e += 64) covm[e] = g_lin[b * LINDIM + e];
    for (int e = tid; e < MDIM * 16; e += 64) {
        int j = e >> 4, kk = e & 15;
        eps_red[e] = eps[(b * MDIM + j) * KPATH + q * 16 + kk];
    }
    __syncthreads();

    // ---- newV for this block's 16 k's (f32x2 over k-pairs) ----
    {
        const int kp = tid & 7;         // k-pair 0..7
        const int ig = tid >> 3;        // 0..7
        for (int i = ig; i < MDIM; i += 8) {
            const int X = i / 3, tr = i % 3;
            const int tbase = 93 + tr * (tr + 1) / 2;
            u64 acc = bc2(covm[i]);
            for (int y = 0; y <= X; y++) {
                const int d = X - y;
                const int blk6 = (31 * d - (d * (d - 1)) / 2 + y) * 6 + tbase;
#pragma unroll
                for (int tc = 0; tc < 3; tc++) {
                    if (tc <= tr) {
                        const u64 ep = *(const u64*)&eps_red[(y * 3 + tc) * 16 + 2 * kp];
                        acc = fma2(bc2(covm[blk6 + tc]), ep, acc);
                    }
                }
            }
            *(u64*)&nvs[i * 16 + 2 * kp] = acc;
        }
    }
    __syncthreads();

    // ---- signature recursion (4 lanes per path, prefetched loads) ----
    const int pk = tid >> 2;        // path 0..15
    const int a  = tid & 3;         // leading tensor index
    const u64 halfb = bc2(0.5f);

    SigP s;
    s.S1 = 0.f;
    s.S2p[0] = s.S2p[1] = 0ull;
#pragma unroll
    for (int i = 0; i < 8; i++)  s.S3p[i] = 0ull;
#pragma unroll
    for (int i = 0; i < 32; i++) s.S4p[i] = 0ull;

    float p0 = xs[0], p1 = xs[1], p2 = xs[2], p3 = xs[96];
    // prefetch first "new" point
    float q0 = nvs[0 * 16 + pk], q1 = nvs[1 * 16 + pk], q2 = nvs[2 * 16 + pk];
    float qt = xs[128];
    for (int m = 0; m < 31; m++) {
        // step: old m -> new m (inputs already in q*)
        float d0 = q0 - p0, d1 = q1 - p1, d2 = q2 - p2, d3 = qt - p3;
        // prefetch old m+1 while chen runs
        float o0 = xs[3 * (m + 1) + 0];
        float o1 = xs[3 * (m + 1) + 1];
        float o2 = xs[3 * (m + 1) + 2];
        float ot = xs[96 + m + 1];
        {
            float da = (a & 2) ? ((a & 1) ? d3 : d2) : ((a & 1) ? d1 : d0);
            chen_step_p(s, d0, d1, d2, d3, da, halfb);
        }
        // step: new m -> old m+1
        d0 = o0 - q0; d1 = o1 - q1; d2 = o2 - q2; d3 = ot - qt;
        // prefetch new m+1
        if (m < 30) {
            q0 = nvs[(3 * m + 3) * 16 + pk];
            q1 = nvs[(3 * m + 4) * 16 + pk];
            q2 = nvs[(3 * m + 5) * 16 + pk];
            qt = xs[128 + m + 1];
        }
        {
            float da = (a & 2) ? ((a & 1) ? d3 : d2) : ((a & 1) ? d1 : d0);
            chen_step_p(s, d0, d1, d2, d3, da, halfb);
        }
        p0 = o0; p1 = o1; p2 = o2; p3 = ot;
    }

    // ---- per-path norms + bisection ----
    float n1 = s.S1 * s.S1;
    float n2 = 0.f, n3 = 0.f, n4 = 0.f;
#pragma unroll
    for (int i = 0; i < 2; i++)  { float lo, hi; unpk2(s.S2p[i], lo, hi); n2 = fmaf(lo, lo, n2); n2 = fmaf(hi, hi, n2); }
#pragma unroll
    for (int i = 0; i < 8; i++)  { float lo, hi; unpk2(s.S3p[i], lo, hi); n3 = fmaf(lo, lo, n3); n3 = fmaf(hi, hi, n3); }
#pragma unroll
    for (int i = 0; i < 32; i++) { float lo, hi; unpk2(s.S4p[i], lo, hi); n4 = fmaf(lo, lo, n4); n4 = fmaf(hi, hi, n4); }
#pragma unroll
    for (int msk = 1; msk <= 2; msk <<= 1) {
        n1 += __shfl_xor_sync(0xffffffffu, n1, msk);
        n2 += __shfl_xor_sync(0xffffffffu, n2, msk);
        n3 += __shfl_xor_sync(0xffffffffu, n3, msk);
        n4 += __shfl_xor_sync(0xffffffffu, n4, msk);
    }
    const float norm2 = 1.f + n1 + n2 + n3 + n4;
    const float psi = (norm2 <= 4.f) ? norm2 : (8.f - 16.f / norm2);
    float lo_ = 0.f, hi_ = 1.f;
    for (int it = 0; it < 30; it++) {   // 2^-30 << fp32 ulp of result
        float mid = 0.5f * (lo_ + hi_);
        float m2 = mid * mid, m4 = m2 * m2;
        float val = 1.f + m2 * n1 + m4 * n2 + (m4 * m2) * n3 + (m4 * m4) * n4;
        bool pos = val > psi;
        hi_ = pos ? mid : hi_;
        lo_ = pos ? lo_ : mid;
    }
    const float lam = 0.5f * (lo_ + hi_);
    const float l2 = lam * lam, l3 = l2 * lam, l4 = l2 * l2;
    s.S1 *= lam;
    const u64 l2b = bc2(l2), l3b = bc2(l3), l4b = bc2(l4);
#pragma unroll
    for (int i = 0; i < 2; i++)  s.S2p[i] = mul2(l2b, s.S2p[i]);
#pragma unroll
    for (int i = 0; i < 8; i++)  s.S3p[i] = mul2(l3b, s.S3p[i]);
#pragma unroll
    for (int i = 0; i < 32; i++) s.S4p[i] = mul2(l4b, s.S4p[i]);

    // ---- reduce the 8 paths of each warp; lanes 0..3 hold slice sums ----
    __syncthreads();                 // eps no longer needed
    float* red = eps_red;            // 2 warps x SIGDIM = 680 <= 1488
    const int w = tid >> 5;
    const int lane = tid & 31;
    {
        float v = s.S1;
        v += __shfl_down_sync(0xffffffffu, v, 16);
        v += __shfl_down_sync(0xffffffffu, v, 8);
        v += __shfl_down_sync(0xffffffffu, v, 4);
        if (lane < 4) red[w * SIGDIM + a] = v;
    }
#pragma unroll
    for (int i = 0; i < 2; i++) {
        u64 v = wredp(s.S2p[i]);
        if (lane < 4) {
            float lo, hi; unpk2(v, lo, hi);
            red[w * SIGDIM + 4 + a * 4 + 2 * i]     = lo;
            red[w * SIGDIM + 4 + a * 4 + 2 * i + 1] = hi;
        }
    }
#pragma unroll
    for (int i = 0; i < 8; i++) {
        const int j = i >> 2, c = i & 3;
        u64 v = wredp(s.S3p[i]);
        if (lane < 4) {
            float lo, hi; unpk2(v, lo, hi);
            red[w * SIGDIM + 20 + a * 16 + (2 * j) * 4 + c]     = lo;
            red[w * SIGDIM + 20 + a * 16 + (2 * j + 1) * 4 + c] = hi;
        }
    }
#pragma unroll
    for (int i = 0; i < 32; i++) {
        const int j = i >> 4, c = (i >> 2) & 3, e = i & 3;
        u64 v = wredp(s.S4p[i]);
        if (lane < 4) {
            float lo, hi; unpk2(v, lo, hi);
            red[w * SIGDIM + 84 + a * 64 + (2 * j) * 16 + c * 4 + e]     = lo;
            red[w * SIGDIM + 84 + a * 64 + (2 * j + 1) * 16 + c * 4 + e] = hi;
        }
    }
    __syncthreads();
    for (int e = tid; e < SIGDIM; e += 64)
        red[e] = red[e] + red[SIGDIM + e];
    __syncthreads();

    // ---- partial logits for this quarter-batch ----
    for (int c = w; c < 10; c += 2) {
        float acc = 0.f;
        for (int sidx = lane; sidx < SIGDIM; sidx += 32)
            acc = fmaf(red[sidx], Wf[c * SIGDIM + sidx], acc);
#pragma unroll
        for (int off = 16; off >= 1; off >>= 1)
            acc += __shfl_xor_sync(0xffffffffu, acc, off);
        if (lane == 0) g_lgt[blk * 10 + c] = acc;
    }
    __syncthreads();

    // ---- arrival counter: 4th block for this b does the softmax ----
    if (tid == 0) {
        __threadfence();
        arrive_s = atomicAdd(&g_cnt[b], 1);
    }
    __syncthreads();
    if (arrive_s == 3 && w == 0) {
        __threadfence();
        float v = -3.0e38f;
        if (lane < 10) {
            float sum = g_lgt[(4 * b) * 10 + lane] + g_lgt[(4 * b + 1) * 10 + lane]
                      + g_lgt[(4 * b + 2) * 10 + lane] + g_lgt[(4 * b + 3) * 10 + lane];
            v = sum * (1.f / 64.f) + bf[lane];
        }
        float mx = v;
#pragma unroll
        for (int off = 16; off >= 1; off >>= 1)
            mx = fmaxf(mx, __shfl_xor_sync(0xffffffffu, mx, off));
        float ex = (lane < 10) ? expf(v - mx) : 0.f;
        float se = ex;
#pragma unroll
        for (int off = 16; off >= 1; off >>= 1)
            se += __shfl_xor_sync(0xffffffffu, se, off);
        const float lse = mx + logf(se);
        if (lane < 10) out[b * 10 + lane] = v - lse;
        if (lane == 0) g_cnt[b] = 0;   // restore for next graph replay
    }
}

// ---------------------------------------------------------------------------
extern "C" void kernel_launch(void* const* d_in, const int* in_sizes, int n_in,
                              void* d_out, int out_size)
{
    const float* x   = (const float*)d_in[0];
    const float* Wm  = (const float*)d_in[1];
    const float* bm  = (const float*)d_in[2];
    const float* Wc  = (const float*)d_in[3];
    const float* bc  = (const float*)d_in[4];
    const float* Wf  = (const float*)d_in[5];
    const float* bf  = (const float*)d_in[6];
    const float* eps = (const float*)d_in[7];
    float* out = (float*)d_out;

    k_linear<<<dim3(24, 8), 128>>>(x, Wm, bm, Wc, bc);
    k_sigf<<<4 * BATCH, 64>>>(x, eps, Wf, bf, out);
}

// round 12
// speedup vs baseline: 1.3129x; 1.1451x over previous
#include <cuda_runtime.h>

#define BATCH   256
#define INDIM   159
#define MDIM    93
#define MATEL   2976
#define LINDIM  (MDIM + MATEL)   /* 3069 */
#define KPATH   64
#define SIGDIM  340

typedef unsigned long long u64;

__device__ float g_lin2[2][BATCH * LINDIM];   // split-K partials
__device__ float g_lgt[4 * BATCH * 10];
__device__ int   g_cnt[BATCH];                // zero-init; restored each run

// ---------------- packed f32x2 helpers (used in k_linear / newV only) ------
__device__ __forceinline__ u64 bc2(float x) {
    u64 r; asm("mov.b64 %0, {%1, %1};" : "=l"(r) : "f"(x)); return r;
}
__device__ __forceinline__ void unpk2(u64 p, float& lo, float& hi) {
    asm("mov.b64 {%0, %1}, %2;" : "=f"(lo), "=f"(hi) : "l"(p));
}
__device__ __forceinline__ u64 fma2(u64 a, u64 b, u64 c) {
    u64 d; asm("fma.rn.f32x2 %0, %1, %2, %3;" : "=l"(d) : "l"(a), "l"(b), "l"(c)); return d;
}

// ---------------------------------------------------------------------------
// Kernel 1: lin partial = x @ W^T (split-K over input dim) + bias (split 0).
// Block 256 thr: 128 rows x 32 batches; thread owns 2 rows x 4 batch-pairs.
// Grid (24, 8, 2).
// ---------------------------------------------------------------------------
__global__ void __launch_bounds__(256) k_linear(
    const float* __restrict__ x,
    const float* __restrict__ Wm, const float* __restrict__ bm,
    const float* __restrict__ Wc, const float* __restrict__ bc)
{
    __shared__ float xt[80][32];        // transposed x tile for this split
    __shared__ float Ws[128][33];
    const int tid = threadIdx.x;
    const int b0  = blockIdx.y * 32;
    const int r0  = blockIdx.x * 128;
    const int sp  = blockIdx.z;
    const int ct_lo = sp ? 80 : 0;
    const int ct_hi = sp ? INDIM : 80;

    const int rowt = tid & 63;          // row pair: rowt, rowt+64
    const int bpt  = tid >> 6;          // 0..3 -> batch pairs 4*bpt+i

    for (int e = tid; e < (ct_hi - ct_lo) * 32; e += 256) {
        int c = e >> 5, bb = e & 31;
        xt[c][bb] = x[(b0 + bb) * INDIM + ct_lo + c];
    }

    u64 acc2[2][4];
#pragma unroll
    for (int j = 0; j < 2; j++) {
        const int rg = r0 + rowt + 64 * j;
        float bias = 0.f;
        if (sp == 0 && rg < LINDIM) bias = (rg < MDIM) ? bm[rg] : bc[rg - MDIM];
        const u64 bb2 = bc2(bias);
#pragma unroll
        for (int i = 0; i < 4; i++) acc2[j][i] = bb2;
    }

    for (int ct = ct_lo; ct < ct_hi; ct += 32) {
        const int cn = min(32, ct_hi - ct);
        __syncthreads();
        for (int e = tid; e < 128 * 32; e += 256) {
            int rr = e >> 5, cc = e & 31;
            int rg = r0 + rr;
            float w = 0.f;
            if (rg < LINDIM && cc < cn)
                w = (rg < MDIM) ? Wm[rg * INDIM + ct + cc]
                                : Wc[(rg - MDIM) * INDIM + ct + cc];
            Ws[rr][cc] = w;
        }
        __syncthreads();
        for (int cc = 0; cc < cn; cc++) {
            u64 w2[2], xp[4];
#pragma unroll
            for (int j = 0; j < 2; j++) w2[j] = bc2(Ws[rowt + 64 * j][cc]);
#pragma unroll
            for (int i = 0; i < 4; i++)
                xp[i] = *(const u64*)&xt[ct - ct_lo + cc][2 * (4 * bpt + i)];
#pragma unroll
            for (int j = 0; j < 2; j++)
#pragma unroll
                for (int i = 0; i < 4; i++)
                    acc2[j][i] = fma2(w2[j], xp[i], acc2[j][i]);
        }
    }
#pragma unroll
    for (int j = 0; j < 2; j++) {
        const int rg = r0 + rowt + 64 * j;
        if (rg < LINDIM) {
#pragma unroll
            for (int i = 0; i < 4; i++) {
                float lo, hi; unpk2(acc2[j][i], lo, hi);
                const int p = 4 * bpt + i;
                g_lin2[sp][(b0 + 2 * p) * LINDIM + rg]     = lo;
                g_lin2[sp][(b0 + 2 * p + 1) * LINDIM + rg] = hi;
            }
        }
    }
}

// ---------------------------------------------------------------------------
// Kernel 2 (fused): newV + signatures + normalization + logits + softmax.
// 256 thr/block, 16 paths/block (quarter of K), grid 4*BATCH = 1024.
// SIG SLICING: 16 lanes per path; lane owns (a = i1, bq = i2).  State per
// lane is PURE SCALAR: S4[c][e] 16, S3[c] 4, S2 1, S1 1  (22 floats).
// ---------------------------------------------------------------------------
__global__ void __launch_bounds__(256, 6) k_sigf(
    const float* __restrict__ x, const float* __restrict__ eps,
    const float* __restrict__ Wf, const float* __restrict__ bf,
    float* __restrict__ out)
{
    __shared__ float xs[INDIM];
    __shared__ float covm[LINDIM];          // mean+cov; re-used as red[8*SIGDIM]
    __shared__ float nvs[MDIM * 16];
    __shared__ float eps_s[MDIM * 16];
    __shared__ int   arrive_s;

    const int blk = blockIdx.x;
    const int b = blk >> 2, q = blk & 3;    // quarter of K
    const int tid = threadIdx.x;

    for (int e = tid; e < INDIM; e += 256) xs[e] = x[b * INDIM + e];
    for (int e = tid; e < LINDIM; e += 256)
        covm[e] = g_lin2[0][b * LINDIM + e] + g_lin2[1][b * LINDIM + e];
    for (int e = tid; e < MDIM * 16; e += 256) {
        int j = e >> 4, kk = e & 15;
        eps_s[e] = eps[(b * MDIM + j) * KPATH + q * 16 + kk];
    }
    __syncthreads();

    // ---- newV for this block's 16 k's (f32x2 over k-pairs) ----
    {
        const int kp = tid & 7;         // k-pair 0..7
        const int ig = tid >> 3;        // 0..31
        for (int i = ig; i < MDIM; i += 32) {
            const int X = i / 3, tr = i % 3;
            const int tbase = 93 + tr * (tr + 1) / 2;
            u64 acc = bc2(covm[i]);
            for (int y = 0; y <= X; y++) {
                const int d = X - y;
                const int blk6 = (31 * d - (d * (d - 1)) / 2 + y) * 6 + tbase;
#pragma unroll
                for (int tc = 0; tc < 3; tc++) {
                    if (tc <= tr) {
                        const u64 ep = *(const u64*)&eps_s[(y * 3 + tc) * 16 + 2 * kp];
                        acc = fma2(bc2(covm[blk6 + tc]), ep, acc);
                    }
                }
            }
            *(u64*)&nvs[i * 16 + 2 * kp] = acc;
        }
    }
    __syncthreads();

    // ---- signature recursion: lane (a, bq), scalar state ----
    const int pk = tid >> 4;        // path 0..15
    const int l16 = tid & 15;
    const int a  = l16 >> 2;        // i1
    const int bq = l16 & 3;         // i2

    float S1 = 0.f, S2 = 0.f;
    float S3[4], S4[16];
#pragma unroll
    for (int i = 0; i < 4; i++)  S3[i] = 0.f;
#pragma unroll
    for (int i = 0; i < 16; i++) S4[i] = 0.f;

    float p0 = xs[0], p1 = xs[1], p2 = xs[2], p3 = xs[96];
    float q0 = nvs[0 * 16 + pk], q1 = nvs[1 * 16 + pk], q2 = nvs[2 * 16 + pk];
    float qt = xs[128];
    for (int m = 0; m < 31; m++) {
#pragma unroll
        for (int half = 0; half < 2; half++) {
            float d0, d1, d2, d3;
            if (half == 0) {
                d0 = q0 - p0; d1 = q1 - p1; d2 = q2 - p2; d3 = qt - p3;
                // prefetch old m+1
                p0 = xs[3 * (m + 1) + 0];
                p1 = xs[3 * (m + 1) + 1];
                p2 = xs[3 * (m + 1) + 2];
                p3 = xs[96 + m + 1];
            } else {
                d0 = p0 - q0; d1 = p1 - q1; d2 = p2 - q2; d3 = p3 - qt;
                if (m < 30) {   // prefetch new m+1
                    q0 = nvs[(3 * m + 3) * 16 + pk];
                    q1 = nvs[(3 * m + 4) * 16 + pk];
                    q2 = nvs[(3 * m + 5) * 16 + pk];
                    qt = xs[128 + m + 1];
                }
            }
            const float da = (a  & 2) ? ((a  & 1) ? d3 : d2) : ((a  & 1) ? d1 : d0);
            const float db = (bq & 2) ? ((bq & 1) ? d3 : d2) : ((bq & 1) ? d1 : d0);

            // level 4: S4[c][e] += (S3[c] + rh*d[c]) * d[e]
            const float g4 = fmaf(0.25f, da, S1) * (1.f / 3.f);
            const float rh = 0.5f * fmaf(g4, db, S2);
            const float dd[4] = { d0, d1, d2, d3 };
#pragma unroll
            for (int c = 0; c < 4; c++) {
                const float t = fmaf(rh, dd[c], S3[c]);
#pragma unroll
                for (int e = 0; e < 4; e++)
                    S4[c * 4 + e] = fmaf(t, dd[e], S4[c * 4 + e]);
            }
            // level 3: S3[c] += (S2 + g3h*d_b) * d[c]
            const float g3h = 0.5f * fmaf(1.f / 3.f, da, S1);
            const float w3 = fmaf(g3h, db, S2);
#pragma unroll
            for (int c = 0; c < 4; c++)
                S3[c] = fmaf(w3, dd[c], S3[c]);
            // level 2 / 1
            S2 = fmaf(fmaf(0.5f, da, S1), db, S2);
            S1 += da;
        }
    }

    // ---- per-path norms: sum over the 16 lanes of this path ----
    float n1 = (bq == 0) ? S1 * S1 : 0.f;
    float n2 = S2 * S2;
    float n3 = 0.f, n4 = 0.f;
#pragma unroll
    for (int i = 0; i < 4; i++)  n3 = fmaf(S3[i], S3[i], n3);
#pragma unroll
    for (int i = 0; i < 16; i++) n4 = fmaf(S4[i], S4[i], n4);
#pragma unroll
    for (int msk = 1; msk <= 8; msk <<= 1) {
        n1 += __shfl_xor_sync(0xffffffffu, n1, msk);
        n2 += __shfl_xor_sync(0xffffffffu, n2, msk);
        n3 += __shfl_xor_sync(0xffffffffu, n3, msk);
        n4 += __shfl_xor_sync(0xffffffffu, n4, msk);
    }
    const float norm2 = 1.f + n1 + n2 + n3 + n4;
    const float psi = (norm2 <= 4.f) ? norm2 : (8.f - 16.f / norm2);
    float lo_ = 0.f, hi_ = 1.f;
    for (int it = 0; it < 30; it++) {
        float mid = 0.5f * (lo_ + hi_);
        float m2 = mid * mid, m4 = m2 * m2;
        float val = 1.f + m2 * n1 + m4 * n2 + (m4 * m2) * n3 + (m4 * m4) * n4;
        bool pos = val > psi;
        hi_ = pos ? mid : hi_;
        lo_ = pos ? lo_ : mid;
    }
    const float lam = 0.5f * (lo_ + hi_);
    const float l2 = lam * lam, l3 = l2 * lam, l4 = l2 * l2;
    S1 *= lam;
    S2 *= l2;
#pragma unroll
    for (int i = 0; i < 4; i++)  S3[i] *= l3;
#pragma unroll
    for (int i = 0; i < 16; i++) S4[i] *= l4;

    // ---- add the warp's two paths (lanes l and l^16 hold same element) ----
    S1 += __shfl_xor_sync(0xffffffffu, S1, 16);
    S2 += __shfl_xor_sync(0xffffffffu, S2, 16);
#pragma unroll
    for (int i = 0; i < 4; i++)  S3[i] += __shfl_xor_sync(0xffffffffu, S3[i], 16);
#pragma unroll
    for (int i = 0; i < 16; i++) S4[i] += __shfl_xor_sync(0xffffffffu, S4[i], 16);

    // ---- per-warp partial into smem red (overlaid on covm) ----
    __syncthreads();                 // covm dead; reuse as red
    float* red = covm;               // 8 * SIGDIM = 2720 <= 3069
    const int w = tid >> 5;
    const int lane = tid & 31;
    if (lane < 16) {
        float* rw = red + w * SIGDIM;
        if (bq == 0) rw[a] = S1;
        rw[4 + a * 4 + bq] = S2;
#pragma unroll
        for (int c = 0; c < 4; c++)
            rw[20 + a * 16 + bq * 4 + c] = S3[c];
#pragma unroll
        for (int c = 0; c < 4; c++)
#pragma unroll
            for (int e = 0; e < 4; e++)
                rw[84 + a * 64 + bq * 16 + c * 4 + e] = S4[c * 4 + e];
    }
    __syncthreads();
    for (int e = tid; e < SIGDIM; e += 256) {
        float sum = 0.f;
#pragma unroll
        for (int ww = 0; ww < 8; ww++) sum += red[ww * SIGDIM + e];
        red[e] = sum;
    }
    __syncthreads();

    // ---- partial logits for this quarter-batch ----
    for (int c = w; c < 10; c += 8) {
        float acc = 0.f;
        for (int sidx = lane; sidx < SIGDIM; sidx += 32)
            acc = fmaf(red[sidx], Wf[c * SIGDIM + sidx], acc);
#pragma unroll
        for (int off = 16; off >= 1; off >>= 1)
            acc += __shfl_xor_sync(0xffffffffu, acc, off);
        if (lane == 0) g_lgt[blk * 10 + c] = acc;
    }
    __syncthreads();

    // ---- arrival counter: 4th block for this b does the softmax ----
    if (tid == 0) {
        __threadfence();
        arrive_s = atomicAdd(&g_cnt[b], 1);
    }
    __syncthreads();
    if (arrive_s == 3 && w == 0) {
        __threadfence();
        float v = -3.0e38f;
        if (lane < 10) {
            float sum = g_lgt[(4 * b) * 10 + lane] + g_lgt[(4 * b + 1) * 10 + lane]
                      + g_lgt[(4 * b + 2) * 10 + lane] + g_lgt[(4 * b + 3) * 10 + lane];
            v = sum * (1.f / 64.f) + bf[lane];
        }
        float mx = v;
#pragma unroll
        for (int off = 16; off >= 1; off >>= 1)
            mx = fmaxf(mx, __shfl_xor_sync(0xffffffffu, mx, off));
        float ex = (lane < 10) ? expf(v - mx) : 0.f;
        float se = ex;
#pragma unroll
        for (int off = 16; off >= 1; off >>= 1)
            se += __shfl_xor_sync(0xffffffffu, se, off);
        const float lse = mx + logf(se);
        if (lane < 10) out[b * 10 + lane] = v - lse;
        if (lane == 0) g_cnt[b] = 0;   // restore for next graph replay
    }
}

// ---------------------------------------------------------------------------
extern "C" void kernel_launch(void* const* d_in, const int* in_sizes, int n_in,
                              void* d_out, int out_size)
{
    const float* x   = (const float*)d_in[0];
    const float* Wm  = (const float*)d_in[1];
    const float* bm  = (const float*)d_in[2];
    const float* Wc  = (const float*)d_in[3];
    const float* bc  = (const float*)d_in[4];
    const float* Wf  = (const float*)d_in[5];
    const float* bf  = (const float*)d_in[6];
    const float* eps = (const float*)d_in[7];
    float* out = (float*)d_out;

    k_linear<<<dim3(24, 8, 2), 256>>>(x, Wm, bm, Wc, bc);
    k_sigf<<<4 * BATCH, 256>>>(x, eps, Wf, bf, out);
}

// round 13
// speedup vs baseline: 1.4888x; 1.1340x over previous
#include <cuda_runtime.h>

#define BATCH   256
#define INDIM   159
#define MDIM    93
#define MATEL   2976
#define LINDIM  (MDIM + MATEL)   /* 3069 */
#define KPATH   64
#define SIGDIM  340

typedef unsigned long long u64;

__device__ float g_lin2[2][BATCH * LINDIM];   // split-K partials
__device__ float g_lgt[4 * BATCH * 10];
__device__ int   g_cnt[BATCH];                // zero-init; restored each run

// ---------------- packed f32x2 helpers (k_linear / newV only) --------------
__device__ __forceinline__ u64 bc2(float x) {
    u64 r; asm("mov.b64 %0, {%1, %1};" : "=l"(r) : "f"(x)); return r;
}
__device__ __forceinline__ void unpk2(u64 p, float& lo, float& hi) {
    asm("mov.b64 {%0, %1}, %2;" : "=f"(lo), "=f"(hi) : "l"(p));
}
__device__ __forceinline__ u64 fma2(u64 a, u64 b, u64 c) {
    u64 d; asm("fma.rn.f32x2 %0, %1, %2, %3;" : "=l"(d) : "l"(a), "l"(b), "l"(c)); return d;
}

// ---------------------------------------------------------------------------
// Kernel 1: lin partial = x @ W^T (split-K over input dim) + bias (split 0).
// Block 256 thr: 128 rows x 32 batches; thread owns 2 rows x 4 batch-pairs.
// Grid (24, 8, 2).
// ---------------------------------------------------------------------------
__global__ void __launch_bounds__(256) k_linear(
    const float* __restrict__ x,
    const float* __restrict__ Wm, const float* __restrict__ bm,
    const float* __restrict__ Wc, const float* __restrict__ bc)
{
    __shared__ float xt[80][32];        // transposed x tile for this split
    __shared__ float Ws[128][33];
    const int tid = threadIdx.x;
    const int b0  = blockIdx.y * 32;
    const int r0  = blockIdx.x * 128;
    const int sp  = blockIdx.z;
    const int ct_lo = sp ? 80 : 0;
    const int ct_hi = sp ? INDIM : 80;

    const int rowt = tid & 63;          // row pair: rowt, rowt+64
    const int bpt  = tid >> 6;          // 0..3 -> batch pairs 4*bpt+i

    for (int e = tid; e < (ct_hi - ct_lo) * 32; e += 256) {
        int c = e >> 5, bb = e & 31;
        xt[c][bb] = x[(b0 + bb) * INDIM + ct_lo + c];
    }

    u64 acc2[2][4];
#pragma unroll
    for (int j = 0; j < 2; j++) {
        const int rg = r0 + rowt + 64 * j;
        float bias = 0.f;
        if (sp == 0 && rg < LINDIM) bias = (rg < MDIM) ? bm[rg] : bc[rg - MDIM];
        const u64 bb2 = bc2(bias);
#pragma unroll
        for (int i = 0; i < 4; i++) acc2[j][i] = bb2;
    }

    for (int ct = ct_lo; ct < ct_hi; ct += 32) {
        const int cn = min(32, ct_hi - ct);
        __syncthreads();
        for (int e = tid; e < 128 * 32; e += 256) {
            int rr = e >> 5, cc = e & 31;
            int rg = r0 + rr;
            float w = 0.f;
            if (rg < LINDIM && cc < cn)
                w = (rg < MDIM) ? Wm[rg * INDIM + ct + cc]
                                : Wc[(rg - MDIM) * INDIM + ct + cc];
            Ws[rr][cc] = w;
        }
        __syncthreads();
        for (int cc = 0; cc < cn; cc++) {
            u64 w2[2], xp[4];
#pragma unroll
            for (int j = 0; j < 2; j++) w2[j] = bc2(Ws[rowt + 64 * j][cc]);
#pragma unroll
            for (int i = 0; i < 4; i++)
                xp[i] = *(const u64*)&xt[ct - ct_lo + cc][2 * (4 * bpt + i)];
#pragma unroll
            for (int j = 0; j < 2; j++)
#pragma unroll
                for (int i = 0; i < 4; i++)
                    acc2[j][i] = fma2(w2[j], xp[i], acc2[j][i]);
        }
    }
#pragma unroll
    for (int j = 0; j < 2; j++) {
        const int rg = r0 + rowt + 64 * j;
        if (rg < LINDIM) {
#pragma unroll
            for (int i = 0; i < 4; i++) {
                float lo, hi; unpk2(acc2[j][i], lo, hi);
                const int p = 4 * bpt + i;
                g_lin2[sp][(b0 + 2 * p) * LINDIM + rg]     = lo;
                g_lin2[sp][(b0 + 2 * p + 1) * LINDIM + rg] = hi;
            }
        }
    }
}

// ---------------------------------------------------------------------------
// Kernel 2 (fused): newV + signatures + normalization + logits + softmax.
// 128 thr/block, 16 paths/block (quarter of K), grid 4*BATCH = 1024.
// 7 blocks/SM -> capacity 1036 >= 1024: exactly ONE wave.
// SIG SLICING: 8 lanes/path; lane owns (a = i1, g = i2-half, bq = 2g+j).
// Pure scalar state: S4[2][16] + S3[2][4] + S2[2] + S1 = 43 floats.
// ---------------------------------------------------------------------------
__global__ void __launch_bounds__(128, 7) k_sigf(
    const float* __restrict__ x, const float* __restrict__ eps,
    const float* __restrict__ Wf, const float* __restrict__ bf,
    float* __restrict__ out)
{
    __shared__ float xs[INDIM];
    __shared__ float covm[LINDIM];          // mean+cov; re-used as red[4*SIGDIM]
    __shared__ float nvs[MDIM * 16];
    __shared__ float eps_s[MDIM * 16];
    __shared__ int   arrive_s;

    const int blk = blockIdx.x;
    const int b = blk >> 2, q = blk & 3;    // quarter of K
    const int tid = threadIdx.x;

    for (int e = tid; e < INDIM; e += 128) xs[e] = x[b * INDIM + e];
    for (int e = tid; e < LINDIM; e += 128)
        covm[e] = g_lin2[0][b * LINDIM + e] + g_lin2[1][b * LINDIM + e];
    for (int e = tid; e < MDIM * 16; e += 128) {
        int j = e >> 4, kk = e & 15;
        eps_s[e] = eps[(b * MDIM + j) * KPATH + q * 16 + kk];
    }
    __syncthreads();

    // ---- newV for this block's 16 k's (f32x2 over k-pairs) ----
    {
        const int kp = tid & 7;         // k-pair 0..7
        const int ig = tid >> 3;        // 0..15
        for (int i = ig; i < MDIM; i += 16) {
            const int X = i / 3, tr = i % 3;
            const int tbase = 93 + tr * (tr + 1) / 2;
            u64 acc = bc2(covm[i]);
            for (int y = 0; y <= X; y++) {
                const int d = X - y;
                const int blk6 = (31 * d - (d * (d - 1)) / 2 + y) * 6 + tbase;
#pragma unroll
                for (int tc = 0; tc < 3; tc++) {
                    if (tc <= tr) {
                        const u64 ep = *(const u64*)&eps_s[(y * 3 + tc) * 16 + 2 * kp];
                        acc = fma2(bc2(covm[blk6 + tc]), ep, acc);
                    }
                }
            }
            *(u64*)&nvs[i * 16 + 2 * kp] = acc;
        }
    }
    __syncthreads();

    // ---- signature recursion: lane (a, g), scalar state ----
    const int pk = tid >> 3;        // path 0..15
    const int l8 = tid & 7;
    const int a  = l8 >> 1;         // i1
    const int g  = l8 & 1;          // i2 half: owns bq = 2g, 2g+1

    float S1 = 0.f;
    float S2[2] = {0.f, 0.f};
    float S3[2][4], S4[2][16];
#pragma unroll
    for (int j = 0; j < 2; j++) {
#pragma unroll
        for (int i = 0; i < 4; i++)  S3[j][i] = 0.f;
#pragma unroll
        for (int i = 0; i < 16; i++) S4[j][i] = 0.f;
    }

    float p0 = xs[0], p1 = xs[1], p2 = xs[2], p3 = xs[96];
    float q0 = nvs[0 * 16 + pk], q1 = nvs[1 * 16 + pk], q2 = nvs[2 * 16 + pk];
    float qt = xs[128];
    for (int m = 0; m < 31; m++) {
#pragma unroll
        for (int half = 0; half < 2; half++) {
            float d0, d1, d2, d3;
            if (half == 0) {
                d0 = q0 - p0; d1 = q1 - p1; d2 = q2 - p2; d3 = qt - p3;
                // prefetch old m+1
                p0 = xs[3 * (m + 1) + 0];
                p1 = xs[3 * (m + 1) + 1];
                p2 = xs[3 * (m + 1) + 2];
                p3 = xs[96 + m + 1];
            } else {
                d0 = p0 - q0; d1 = p1 - q1; d2 = p2 - q2; d3 = p3 - qt;
                if (m < 30) {   // prefetch new m+1
                    q0 = nvs[(3 * m + 3) * 16 + pk];
                    q1 = nvs[(3 * m + 4) * 16 + pk];
                    q2 = nvs[(3 * m + 5) * 16 + pk];
                    qt = xs[128 + m + 1];
                }
            }
            const float da  = (a & 2) ? ((a & 1) ? d3 : d2) : ((a & 1) ? d1 : d0);
            const float db0 = g ? d2 : d0;
            const float db1 = g ? d3 : d1;

            const float g4  = fmaf(0.25f, da, S1) * (1.f / 3.f);
            const float g3h = 0.5f * fmaf(1.f / 3.f, da, S1);
            const float g2  = fmaf(0.5f, da, S1);
            const float rh0 = 0.5f * fmaf(g4, db0, S2[0]);
            const float rh1 = 0.5f * fmaf(g4, db1, S2[1]);
            const float w30 = fmaf(g3h, db0, S2[0]);
            const float w31 = fmaf(g3h, db1, S2[1]);

            const float dd0 = d0, dd1 = d1, dd2 = d2, dd3 = d3;
#pragma unroll
            for (int c = 0; c < 4; c++) {
                const float dc = (c == 0) ? dd0 : (c == 1) ? dd1 : (c == 2) ? dd2 : dd3;
                // level 4
                const float t0 = fmaf(rh0, dc, S3[0][c]);
                const float t1 = fmaf(rh1, dc, S3[1][c]);
                S4[0][c * 4 + 0] = fmaf(t0, dd0, S4[0][c * 4 + 0]);
                S4[0][c * 4 + 1] = fmaf(t0, dd1, S4[0][c * 4 + 1]);
                S4[0][c * 4 + 2] = fmaf(t0, dd2, S4[0][c * 4 + 2]);
                S4[0][c * 4 + 3] = fmaf(t0, dd3, S4[0][c * 4 + 3]);
                S4[1][c * 4 + 0] = fmaf(t1, dd0, S4[1][c * 4 + 0]);
                S4[1][c * 4 + 1] = fmaf(t1, dd1, S4[1][c * 4 + 1]);
                S4[1][c * 4 + 2] = fmaf(t1, dd2, S4[1][c * 4 + 2]);
                S4[1][c * 4 + 3] = fmaf(t1, dd3, S4[1][c * 4 + 3]);
                // level 3
                S3[0][c] = fmaf(w30, dc, S3[0][c]);
                S3[1][c] = fmaf(w31, dc, S3[1][c]);
            }
            // level 2 / 1
            S2[0] = fmaf(g2, db0, S2[0]);
            S2[1] = fmaf(g2, db1, S2[1]);
            S1 += da;
        }
    }

    // ---- per-path norms: sum over the 8 lanes of this path ----
    float n1 = (g == 0) ? S1 * S1 : 0.f;
    float n2 = fmaf(S2[0], S2[0], S2[1] * S2[1]);
    float n3 = 0.f, n4 = 0.f;
#pragma unroll
    for (int j = 0; j < 2; j++) {
#pragma unroll
        for (int i = 0; i < 4; i++)  n3 = fmaf(S3[j][i], S3[j][i], n3);
#pragma unroll
        for (int i = 0; i < 16; i++) n4 = fmaf(S4[j][i], S4[j][i], n4);
    }
#pragma unroll
    for (int msk = 1; msk <= 4; msk <<= 1) {
        n1 += __shfl_xor_sync(0xffffffffu, n1, msk);
        n2 += __shfl_xor_sync(0xffffffffu, n2, msk);
        n3 += __shfl_xor_sync(0xffffffffu, n3, msk);
        n4 += __shfl_xor_sync(0xffffffffu, n4, msk);
    }
    const float norm2 = 1.f + n1 + n2 + n3 + n4;
    const float psi = (norm2 <= 4.f) ? norm2 : (8.f - 16.f / norm2);
    float lo_ = 0.f, hi_ = 1.f;
    for (int it = 0; it < 30; it++) {
        float mid = 0.5f * (lo_ + hi_);
        float m2 = mid * mid, m4 = m2 * m2;
        float val = 1.f + m2 * n1 + m4 * n2 + (m4 * m2) * n3 + (m4 * m4) * n4;
        bool pos = val > psi;
        hi_ = pos ? mid : hi_;
        lo_ = pos ? lo_ : mid;
    }
    const float lam = 0.5f * (lo_ + hi_);
    const float l2 = lam * lam, l3 = l2 * lam, l4 = l2 * l2;
    S1 *= lam;
#pragma unroll
    for (int j = 0; j < 2; j++) {
        S2[j] *= l2;
#pragma unroll
        for (int i = 0; i < 4; i++)  S3[j][i] *= l3;
#pragma unroll
        for (int i = 0; i < 16; i++) S4[j][i] *= l4;
    }

    // ---- sum the 4 paths of this warp into every lane ----
#pragma unroll
    for (int msk = 8; msk <= 16; msk <<= 1) {
        S1 += __shfl_xor_sync(0xffffffffu, S1, msk);
#pragma unroll
        for (int j = 0; j < 2; j++) {
            S2[j] += __shfl_xor_sync(0xffffffffu, S2[j], msk);
#pragma unroll
            for (int i = 0; i < 4; i++)
                S3[j][i] += __shfl_xor_sync(0xffffffffu, S3[j][i], msk);
#pragma unroll
            for (int i = 0; i < 16; i++)
                S4[j][i] += __shfl_xor_sync(0xffffffffu, S4[j][i], msk);
        }
    }

    // ---- per-warp partial into smem red (overlaid on covm) ----
    __syncthreads();                 // covm dead; reuse as red
    float* red = covm;               // 4 * SIGDIM = 1360 <= 3069
    const int w = tid >> 5;
    const int lane = tid & 31;
    if (lane < 8) {
        float* rw = red + w * SIGDIM;
        if (g == 0) rw[a] = S1;
#pragma unroll
        for (int j = 0; j < 2; j++) {
            const int bq = 2 * g + j;
            rw[4 + a * 4 + bq] = S2[j];
#pragma unroll
            for (int c = 0; c < 4; c++)
                rw[20 + a * 16 + bq * 4 + c] = S3[j][c];
#pragma unroll
            for (int c = 0; c < 4; c++)
#pragma unroll
                for (int e = 0; e < 4; e++)
                    rw[84 + a * 64 + bq * 16 + c * 4 + e] = S4[j][c * 4 + e];
        }
    }
    __syncthreads();
    for (int e = tid; e < SIGDIM; e += 128) {
        float sum = red[e] + red[SIGDIM + e] + red[2 * SIGDIM + e] + red[3 * SIGDIM + e];
        red[e] = sum;
    }
    __syncthreads();

    // ---- partial logits for this quarter-batch ----
    for (int c = w; c < 10; c += 4) {
        float acc = 0.f;
        for (int sidx = lane; sidx < SIGDIM; sidx += 32)
            acc = fmaf(red[sidx], Wf[c * SIGDIM + sidx], acc);
#pragma unroll
        for (int off = 16; off >= 1; off >>= 1)
            acc += __shfl_xor_sync(0xffffffffu, acc, off);
        if (lane == 0) g_lgt[blk * 10 + c] = acc;
    }
    __syncthreads();

    // ---- arrival counter: 4th block for this b does the softmax ----
    if (tid == 0) {
        __threadfence();
        arrive_s = atomicAdd(&g_cnt[b], 1);
    }
    __syncthreads();
    if (arrive_s == 3 && w == 0) {
        __threadfence();
        float v = -3.0e38f;
        if (lane < 10) {
            float sum = g_lgt[(4 * b) * 10 + lane] + g_lgt[(4 * b + 1) * 10 + lane]
                      + g_lgt[(4 * b + 2) * 10 + lane] + g_lgt[(4 * b + 3) * 10 + lane];
            v = sum * (1.f / 64.f) + bf[lane];
        }
        float mx = v;
#pragma unroll
        for (int off = 16; off >= 1; off >>= 1)
            mx = fmaxf(mx, __shfl_xor_sync(0xffffffffu, mx, off));
        float ex = (lane < 10) ? expf(v - mx) : 0.f;
        float se = ex;
#pragma unroll
        for (int off = 16; off >= 1; off >>= 1)
            se += __shfl_xor_sync(0xffffffffu, se, off);
        const float lse = mx + logf(se);
        if (lane < 10) out[b * 10 + lane] = v - lse;
        if (lane == 0) g_cnt[b] = 0;   // restore for next graph replay
    }
}

// ---------------------------------------------------------------------------
extern "C" void kernel_launch(void* const* d_in, const int* in_sizes, int n_in,
                              void* d_out, int out_size)
{
    const float* x   = (const float*)d_in[0];
    const float* Wm  = (const float*)d_in[1];
    const float* bm  = (const float*)d_in[2];
    const float* Wc  = (const float*)d_in[3];
    const float* bc  = (const float*)d_in[4];
    const float* Wf  = (const float*)d_in[5];
    const float* bf  = (const float*)d_in[6];
    const float* eps = (const float*)d_in[7];
    float* out = (float*)d_out;

    k_linear<<<dim3(24, 8, 2), 256>>>(x, Wm, bm, Wc, bc);
    k_sigf<<<4 * BATCH, 128>>>(x, eps, Wf, bf, out);
}

// round 14
// speedup vs baseline: 1.4940x; 1.0034x over previous
#include <cuda_runtime.h>

#define BATCH   256
#define INDIM   159
#define MDIM    93
#define MATEL   2976
#define LINDIM  (MDIM + MATEL)   /* 3069 */
#define KPATH   64
#define SIGDIM  340

typedef unsigned long long u64;

__device__ float g_lin2[2][BATCH * LINDIM];   // split-K partials
__device__ float g_lgt[4 * BATCH * 10];
__device__ int   g_cnt[BATCH];                // zero-init; restored each run

// ---------------- packed f32x2 helpers (k_linear / newV only) --------------
__device__ __forceinline__ u64 bc2(float x) {
    u64 r; asm("mov.b64 %0, {%1, %1};" : "=l"(r) : "f"(x)); return r;
}
__device__ __forceinline__ void unpk2(u64 p, float& lo, float& hi) {
    asm("mov.b64 {%0, %1}, %2;" : "=f"(lo), "=f"(hi) : "l"(p));
}
__device__ __forceinline__ u64 fma2(u64 a, u64 b, u64 c) {
    u64 d; asm("fma.rn.f32x2 %0, %1, %2, %3;" : "=l"(d) : "l"(a), "l"(b), "l"(c)); return d;
}

// ---------------------------------------------------------------------------
// Kernel 1: lin partial = x @ W^T (split-K over input dim) + bias (split 0).
// ---------------------------------------------------------------------------
__global__ void __launch_bounds__(256) k_linear(
    const float* __restrict__ x,
    const float* __restrict__ Wm, const float* __restrict__ bm,
    const float* __restrict__ Wc, const float* __restrict__ bc)
{
    __shared__ float xt[80][32];        // transposed x tile for this split
    __shared__ float Ws[128][33];
    const int tid = threadIdx.x;
    const int b0  = blockIdx.y * 32;
    const int r0  = blockIdx.x * 128;
    const int sp  = blockIdx.z;
    const int ct_lo = sp ? 80 : 0;
    const int ct_hi = sp ? INDIM : 80;

    const int rowt = tid & 63;          // row pair: rowt, rowt+64
    const int bpt  = tid >> 6;          // 0..3 -> batch pairs 4*bpt+i

    for (int e = tid; e < (ct_hi - ct_lo) * 32; e += 256) {
        int c = e >> 5, bb = e & 31;
        xt[c][bb] = x[(b0 + bb) * INDIM + ct_lo + c];
    }

    u64 acc2[2][4];
#pragma unroll
    for (int j = 0; j < 2; j++) {
        const int rg = r0 + rowt + 64 * j;
        float bias = 0.f;
        if (sp == 0 && rg < LINDIM) bias = (rg < MDIM) ? bm[rg] : bc[rg - MDIM];
        const u64 bb2 = bc2(bias);
#pragma unroll
        for (int i = 0; i < 4; i++) acc2[j][i] = bb2;
    }

    for (int ct = ct_lo; ct < ct_hi; ct += 32) {
        const int cn = min(32, ct_hi - ct);
        __syncthreads();
        for (int e = tid; e < 128 * 32; e += 256) {
            int rr = e >> 5, cc = e & 31;
            int rg = r0 + rr;
            float w = 0.f;
            if (rg < LINDIM && cc < cn)
                w = (rg < MDIM) ? Wm[rg * INDIM + ct + cc]
                                : Wc[(rg - MDIM) * INDIM + ct + cc];
            Ws[rr][cc] = w;
        }
        __syncthreads();
        for (int cc = 0; cc < cn; cc++) {
            u64 w2[2], xp[4];
#pragma unroll
            for (int j = 0; j < 2; j++) w2[j] = bc2(Ws[rowt + 64 * j][cc]);
#pragma unroll
            for (int i = 0; i < 4; i++)
                xp[i] = *(const u64*)&xt[ct - ct_lo + cc][2 * (4 * bpt + i)];
#pragma unroll
            for (int j = 0; j < 2; j++)
#pragma unroll
                for (int i = 0; i < 4; i++)
                    acc2[j][i] = fma2(w2[j], xp[i], acc2[j][i]);
        }
    }
#pragma unroll
    for (int j = 0; j < 2; j++) {
        const int rg = r0 + rowt + 64 * j;
        if (rg < LINDIM) {
#pragma unroll
            for (int i = 0; i < 4; i++) {
                float lo, hi; unpk2(acc2[j][i], lo, hi);
                const int p = 4 * bpt + i;
                g_lin2[sp][(b0 + 2 * p) * LINDIM + rg]     = lo;
                g_lin2[sp][(b0 + 2 * p + 1) * LINDIM + rg] = hi;
            }
        }
    }
}

// ---------------------------------------------------------------------------
// Kernel 2 (fused): newV + signatures + normalization + logits + softmax.
// 64 thr/block, 16 paths (quarter of K), grid 4*BATCH = 1024.
// 7 blocks/SM -> capacity 1036 >= 1024: ONE wave.  Reg cap 146: no spills.
// 4 lanes/path, lane owns leading index a; PURE SCALAR state:
//   S1a, S2a[4], S3a[16], S4a[64]  (85 floats).
// ---------------------------------------------------------------------------
__global__ void __launch_bounds__(64, 7) k_sigf(
    const float* __restrict__ x, const float* __restrict__ eps,
    const float* __restrict__ Wf, const float* __restrict__ bf,
    float* __restrict__ out)
{
    __shared__ float xs[INDIM];
    __shared__ float covm[LINDIM];          // mean+cov; re-used as red[2*SIGDIM]
    __shared__ float nvs[MDIM * 16];
    __shared__ float eps_s[MDIM * 16];
    __shared__ int   arrive_s;

    const int blk = blockIdx.x;
    const int b = blk >> 2, q = blk & 3;    // quarter of K
    const int tid = threadIdx.x;

    for (int e = tid; e < INDIM; e += 64) xs[e] = x[b * INDIM + e];
    for (int e = tid; e < LINDIM; e += 64)
        covm[e] = g_lin2[0][b * LINDIM + e] + g_lin2[1][b * LINDIM + e];
    for (int e = tid; e < MDIM * 16; e += 64) {
        int j = e >> 4, kk = e & 15;
        eps_s[e] = eps[(b * MDIM + j) * KPATH + q * 16 + kk];
    }
    __syncthreads();

    // ---- newV for this block's 16 k's (f32x2 over k-pairs) ----
    {
        const int kp = tid & 7;         // k-pair 0..7
        const int ig = tid >> 3;        // 0..7
        for (int i = ig; i < MDIM; i += 8) {
            const int X = i / 3, tr = i % 3;
            const int tbase = 93 + tr * (tr + 1) / 2;
            u64 acc = bc2(covm[i]);
            for (int y = 0; y <= X; y++) {
                const int d = X - y;
                const int blk6 = (31 * d - (d * (d - 1)) / 2 + y) * 6 + tbase;
#pragma unroll
                for (int tc = 0; tc < 3; tc++) {
                    if (tc <= tr) {
                        const u64 ep = *(const u64*)&eps_s[(y * 3 + tc) * 16 + 2 * kp];
                        acc = fma2(bc2(covm[blk6 + tc]), ep, acc);
                    }
                }
            }
            *(u64*)&nvs[i * 16 + 2 * kp] = acc;
        }
    }
    __syncthreads();

    // ---- signature recursion: 4 lanes/path, scalar state ----
    const int pk = tid >> 2;        // path 0..15
    const int a  = tid & 3;         // leading tensor index

    float S1a = 0.f;
    float S2a[4], S3a[16], S4a[64];
#pragma unroll
    for (int i = 0; i < 4; i++)  S2a[i] = 0.f;
#pragma unroll
    for (int i = 0; i < 16; i++) S3a[i] = 0.f;
#pragma unroll
    for (int i = 0; i < 64; i++) S4a[i] = 0.f;

    float p0 = xs[0], p1 = xs[1], p2 = xs[2], p3 = xs[96];
    float q0 = nvs[0 * 16 + pk], q1 = nvs[1 * 16 + pk], q2 = nvs[2 * 16 + pk];
    float qt = xs[128];
    for (int m = 0; m < 31; m++) {
#pragma unroll
        for (int half = 0; half < 2; half++) {
            float d0, d1, d2, d3;
            if (half == 0) {
                d0 = q0 - p0; d1 = q1 - p1; d2 = q2 - p2; d3 = qt - p3;
                // prefetch old m+1
                p0 = xs[3 * (m + 1) + 0];
                p1 = xs[3 * (m + 1) + 1];
                p2 = xs[3 * (m + 1) + 2];
                p3 = xs[96 + m + 1];
            } else {
                d0 = p0 - q0; d1 = p1 - q1; d2 = p2 - q2; d3 = p3 - qt;
                if (m < 30) {   // prefetch new m+1
                    q0 = nvs[(3 * m + 3) * 16 + pk];
                    q1 = nvs[(3 * m + 4) * 16 + pk];
                    q2 = nvs[(3 * m + 5) * 16 + pk];
                    qt = xs[128 + m + 1];
                }
            }
            const float dd[4] = { d0, d1, d2, d3 };
            const float da = (a & 2) ? ((a & 1) ? d3 : d2) : ((a & 1) ? d1 : d0);

            const float hd0 = 0.5f * d0, hd1 = 0.5f * d1;
            const float hd2 = 0.5f * d2, hd3 = 0.5f * d3;
            const float hh[4] = { hd0, hd1, hd2, hd3 };

            // level 4: S4[bq][c][e] += (S3[bq][c] + r[bq]*hd[c]) * d[e]
            //   r[bq] = S2[bq] + g4*d[bq]
            const float g4 = fmaf(0.25f, da, S1a) * (1.f / 3.f);
            float r[4];
#pragma unroll
            for (int bq = 0; bq < 4; bq++) r[bq] = fmaf(g4, dd[bq], S2a[bq]);
#pragma unroll
            for (int bq = 0; bq < 4; bq++) {
#pragma unroll
                for (int c = 0; c < 4; c++) {
                    const float t = fmaf(r[bq], hh[c], S3a[bq * 4 + c]);
                    S4a[(bq * 4 + c) * 4 + 0] = fmaf(t, d0, S4a[(bq * 4 + c) * 4 + 0]);
                    S4a[(bq * 4 + c) * 4 + 1] = fmaf(t, d1, S4a[(bq * 4 + c) * 4 + 1]);
                    S4a[(bq * 4 + c) * 4 + 2] = fmaf(t, d2, S4a[(bq * 4 + c) * 4 + 2]);
                    S4a[(bq * 4 + c) * 4 + 3] = fmaf(t, d3, S4a[(bq * 4 + c) * 4 + 3]);
                }
            }
            // level 3: S3[bq][c] += (S2[bq] + g3h*d[bq]) * d[c]
            const float g3h = 0.5f * fmaf(1.f / 3.f, da, S1a);
            float w3[4];
#pragma unroll
            for (int bq = 0; bq < 4; bq++) w3[bq] = fmaf(g3h, dd[bq], S2a[bq]);
#pragma unroll
            for (int bq = 0; bq < 4; bq++) {
                S3a[bq * 4 + 0] = fmaf(w3[bq], d0, S3a[bq * 4 + 0]);
                S3a[bq * 4 + 1] = fmaf(w3[bq], d1, S3a[bq * 4 + 1]);
                S3a[bq * 4 + 2] = fmaf(w3[bq], d2, S3a[bq * 4 + 2]);
                S3a[bq * 4 + 3] = fmaf(w3[bq], d3, S3a[bq * 4 + 3]);
            }
            // level 2 / 1
            const float g2 = fmaf(0.5f, da, S1a);
#pragma unroll
            for (int bq = 0; bq < 4; bq++) S2a[bq] = fmaf(g2, dd[bq], S2a[bq]);
            S1a += da;
        }
    }

    // ---- per-path norms (4 lanes hold complementary slices) ----
    float n1 = S1a * S1a;
    float n2 = 0.f, n3 = 0.f, n4 = 0.f;
#pragma unroll
    for (int i = 0; i < 4; i++)  n2 = fmaf(S2a[i], S2a[i], n2);
#pragma unroll
    for (int i = 0; i < 16; i++) n3 = fmaf(S3a[i], S3a[i], n3);
#pragma unroll
    for (int i = 0; i < 64; i++) n4 = fmaf(S4a[i], S4a[i], n4);
#pragma unroll
    for (int msk = 1; msk <= 2; msk <<= 1) {
        n1 += __shfl_xor_sync(0xffffffffu, n1, msk);
        n2 += __shfl_xor_sync(0xffffffffu, n2, msk);
        n3 += __shfl_xor_sync(0xffffffffu, n3, msk);
        n4 += __shfl_xor_sync(0xffffffffu, n4, msk);
    }
    const float norm2 = 1.f + n1 + n2 + n3 + n4;
    const float psi = (norm2 <= 4.f) ? norm2 : (8.f - 16.f / norm2);
    float lo_ = 0.f, hi_ = 1.f;
    for (int it = 0; it < 30; it++) {
        float mid = 0.5f * (lo_ + hi_);
        float m2 = mid * mid, m4 = m2 * m2;
        float val = 1.f + m2 * n1 + m4 * n2 + (m4 * m2) * n3 + (m4 * m4) * n4;
        bool pos = val > psi;
        hi_ = pos ? mid : hi_;
        lo_ = pos ? lo_ : mid;
    }
    const float lam = 0.5f * (lo_ + hi_);
    const float l2 = lam * lam, l3 = l2 * lam, l4 = l2 * l2;
    S1a *= lam;
#pragma unroll
    for (int i = 0; i < 4; i++)  S2a[i] *= l2;
#pragma unroll
    for (int i = 0; i < 16; i++) S3a[i] *= l3;
#pragma unroll
    for (int i = 0; i < 64; i++) S4a[i] *= l4;

    // ---- reduce the 8 paths of each warp; lanes 0..3 hold slice sums ----
    __syncthreads();                 // covm dead; reuse as red
    float* red = covm;               // 2 * SIGDIM = 680 <= 3069
    const int w = tid >> 5;
    const int lane = tid & 31;
#define WRED(v) do { \
        (v) += __shfl_down_sync(0xffffffffu, (v), 16); \
        (v) += __shfl_down_sync(0xffffffffu, (v), 8);  \
        (v) += __shfl_down_sync(0xffffffffu, (v), 4);  \
    } while (0)
    {
        float v = S1a; WRED(v);
        if (lane < 4) red[w * SIGDIM + a] = v;
    }
#pragma unroll
    for (int i = 0; i < 4; i++) {
        float v = S2a[i]; WRED(v);
        if (lane < 4) red[w * SIGDIM + 4 + a * 4 + i] = v;
    }
#pragma unroll
    for (int i = 0; i < 16; i++) {
        float v = S3a[i]; WRED(v);
        if (lane < 4) red[w * SIGDIM + 20 + a * 16 + i] = v;
    }
#pragma unroll
    for (int i = 0; i < 64; i++) {
        float v = S4a[i]; WRED(v);
        if (lane < 4) red[w * SIGDIM + 84 + a * 64 + i] = v;
    }
#undef WRED
    __syncthreads();
    for (int e = tid; e < SIGDIM; e += 64)
        red[e] = red[e] + red[SIGDIM + e];
    __syncthreads();

    // ---- partial logits for this quarter-batch ----
    for (int c = w; c < 10; c += 2) {
        float acc = 0.f;
        for (int sidx = lane; sidx < SIGDIM; sidx += 32)
            acc = fmaf(red[sidx], Wf[c * SIGDIM + sidx], acc);
#pragma unroll
        for (int off = 16; off >= 1; off >>= 1)
            acc += __shfl_xor_sync(0xffffffffu, acc, off);
        if (lane == 0) g_lgt[blk * 10 + c] = acc;
    }
    __syncthreads();

    // ---- arrival counter: 4th block for this b does the softmax ----
    if (tid == 0) {
        __threadfence();
        arrive_s = atomicAdd(&g_cnt[b], 1);
    }
    __syncthreads();
    if (arrive_s == 3 && w == 0) {
        __threadfence();
        float v = -3.0e38f;
        if (lane < 10) {
            float sum = g_lgt[(4 * b) * 10 + lane] + g_lgt[(4 * b + 1) * 10 + lane]
                      + g_lgt[(4 * b + 2) * 10 + lane] + g_lgt[(4 * b + 3) * 10 + lane];
            v = sum * (1.f / 64.f) + bf[lane];
        }
        float mx = v;
#pragma unroll
        for (int off = 16; off >= 1; off >>= 1)
            mx = fmaxf(mx, __shfl_xor_sync(0xffffffffu, mx, off));
        float ex = (lane < 10) ? expf(v - mx) : 0.f;
        float se = ex;
#pragma unroll
        for (int off = 16; off >= 1; off >>= 1)
            se += __shfl_xor_sync(0xffffffffu, se, off);
        const float lse = mx + logf(se);
        if (lane < 10) out[b * 10 + lane] = v - lse;
        if (lane == 0) g_cnt[b] = 0;   // restore for next graph replay
    }
}

// ---------------------------------------------------------------------------
extern "C" void kernel_launch(void* const* d_in, const int* in_sizes, int n_in,
                              void* d_out, int out_size)
{
    const float* x   = (const float*)d_in[0];
    const float* Wm  = (const float*)d_in[1];
    const float* bm  = (const float*)d_in[2];
    const float* Wc  = (const float*)d_in[3];
    const float* bc  = (const float*)d_in[4];
    const float* Wf  = (const float*)d_in[5];
    const float* bf  = (const float*)d_in[6];
    const float* eps = (const float*)d_in[7];
    float* out = (float*)d_out;

    k_linear<<<dim3(24, 8, 2), 256>>>(x, Wm, bm, Wc, bc);
    k_sigf<<<4 * BATCH, 64>>>(x, eps, Wf, bf, out);
}